// round 4
// baseline (speedup 1.0000x reference)
#include <cuda_runtime.h>
#include <cstdint>
#include <cstddef>

#define BATCH 4096
#define SEQ   60
#define HID   128
#define GATES 512
#define MROWS (BATCH*SEQ)
#define BT    28
#define BPAD  29
#define K0    142            // 13 + 1 + 128
#define K12   385            // 256 + 1 + 128
#define SEG0  (2*K0*GATES)
#define SEG12 (K12*GATES)
#define TOTALW (SEG0 + 4*SEG12)

__device__ float g_y0[(size_t)MROWS * 256];
__device__ float g_y1[(size_t)MROWS * 256];
__device__ float g_wc[TOTALW];

typedef unsigned long long ull;

__device__ __forceinline__ ull pack_dup(float x) {
    ull r; asm("mov.b64 %0, {%1, %1};" : "=l"(r) : "f"(x)); return r;
}
__device__ __forceinline__ ull pack2(float x, float y) {
    ull r; asm("mov.b64 %0, {%1, %2};" : "=l"(r) : "f"(x), "f"(y)); return r;
}
__device__ __forceinline__ void unpack2(ull v, float& x, float& y) {
    asm("mov.b64 {%0, %1}, %2;" : "=f"(x), "=f"(y) : "l"(v));
}
__device__ __forceinline__ void fma2(ull& d, ull a, ull b) {
    asm("fma.rn.f32x2 %0, %1, %2, %3;" : "=l"(d) : "l"(a), "l"(b), "l"(d));
}
__device__ __forceinline__ float sigf(float x) { return __fdividef(1.f, 1.f + __expf(-x)); }
__device__ __forceinline__ float tanhf_(float x) {
    float ax = fabsf(x); float e = __expf(-2.f * ax);
    return copysignf(__fdividef(1.f - e, 1.f + e), x);
}

struct WPtrs {
    const float* w_ih[6];
    const float* w_hh[6];
    const float* b_ih[6];
    const float* b_hh[6];
};

// Build packed combined weights: per (layer,dir) segment of K rows x 512,
// row r: r<IN -> w_ih^T row, r==IN -> b_ih+b_hh, else w_hh^T row (r-IN-1).
// Within a row, col i = p*8 + g*2 + e maps to gate element j = g*128 + p*2 + e,
// so each thread's 4 gate-pairs are 8 consecutive floats (2x LDG.128).
__global__ void prep_kernel(WPtrs P, float* __restrict__ wc) {
    int idx = blockIdx.x * 256 + threadIdx.x;
    if (idx >= TOTALW) return;
    int layer, dir, rem, IN;
    if (idx < SEG0) {
        layer = 0; dir = idx / (K0 * GATES); rem = idx % (K0 * GATES); IN = 13;
    } else {
        int t = idx - SEG0; int ld = t / SEG12;
        layer = 1 + (ld >> 1); dir = ld & 1; rem = t % SEG12; IN = 256;
    }
    int r = rem / GATES, i = rem % GATES;
    int p = i >> 3, g = (i & 7) >> 1, e = i & 1;
    int j = g * 128 + p * 2 + e;
    int w = layer * 2 + dir;
    float v;
    if (r < IN)       v = P.w_ih[w][j * IN + r];
    else if (r == IN) v = P.b_ih[w][j] + P.b_hh[w][j];
    else              v = P.w_hh[w][j * HID + (r - IN - 1)];
    wc[idx] = v;
}

__global__ void dummy_kernel() {}

// stage input rows for timestep t into hs rows [0, IN)
template<int IN>
__device__ __forceinline__ void stage_x(const float* __restrict__ src, float* hs,
                                        int b0, int t, int tid) {
    if (IN == 256) {
        for (int i = tid; i < BT * 128; i += 256) {
            int b = i >> 7; int q = (i & 127) * 2;
            int gb = b0 + b; gb = gb < BATCH - 1 ? gb : BATCH - 1;
            float2 v = *reinterpret_cast<const float2*>(&src[((size_t)gb * SEQ + t) * 256 + q]);
            hs[q * BPAD + b] = v.x;
            hs[(q + 1) * BPAD + b] = v.y;
        }
    } else {
        for (int i = tid; i < BT * IN; i += 256) {
            int b = i / IN, q = i % IN;
            int gb = b0 + b; gb = gb < BATCH - 1 ? gb : BATCH - 1;
            hs[q * BPAD + b] = src[((size_t)gb * SEQ + t) * IN + q];
        }
    }
}

// One bi-dir LSTM layer, input projection + bias + recurrence all fused.
// dir = blockIdx.y; 28 batch rows per CTA; K = IN + 1 + 128 k-rows per step.
template<int IN>
__global__ __launch_bounds__(256, 2)
void lstm_fused(const float* __restrict__ src,   // [B][SEQ][IN]
                const float* __restrict__ wcL,   // [2][K][512] packed
                float* __restrict__ y)           // [B][SEQ][256]
{
    constexpr int K = IN + 129;
    const int dir = blockIdx.y;
    const int b0  = blockIdx.x * BT;
    const int tid = threadIdx.x;
    const int bg  = tid >> 6;          // 0..3, 7 batch rows each
    const int p   = tid & 63;
    const int hc0 = p * 2;
    const float* wcd = wcL + (size_t)dir * K * GATES;

    __shared__ float hs[K * BPAD];

    for (int i = tid; i < K * BPAD; i += 256) hs[i] = 0.f;
    if (tid < BT) hs[IN * BPAD + tid] = 1.f;     // bias row: x == 1

    ull c2[7];
#pragma unroll
    for (int i = 0; i < 7; i++) c2[i] = 0ull;

    stage_x<IN>(src, hs, b0, dir ? SEQ - 1 : 0, tid);
    __syncthreads();

    for (int s = 0; s < SEQ; ++s) {
        const int t = dir ? (SEQ - 1 - s) : s;
        ull acc[7][4];
#pragma unroll
        for (int i = 0; i < 7; i++)
#pragma unroll
            for (int j = 0; j < 4; j++) acc[i][j] = 0ull;

#pragma unroll 4
        for (int k = 0; k < K; ++k) {
            const ull* wr = reinterpret_cast<const ull*>(wcd + (size_t)k * GATES + p * 8);
            ull wv0 = wr[0], wv1 = wr[1], wv2 = wr[2], wv3 = wr[3];
            const float* hrow = &hs[k * BPAD + bg * 7];
#pragma unroll
            for (int bb = 0; bb < 7; ++bb) {
                ull hv = pack_dup(hrow[bb]);
                fma2(acc[bb][0], hv, wv0); fma2(acc[bb][1], hv, wv1);
                fma2(acc[bb][2], hv, wv2); fma2(acc[bb][3], hv, wv3);
            }
        }
        __syncthreads();   // all reads of hs done

#pragma unroll
        for (int bb = 0; bb < 7; ++bb) {
            float i0, i1, f0, f1, g0, g1, o0, o1, cc0, cc1;
            unpack2(acc[bb][0], i0, i1); unpack2(acc[bb][1], f0, f1);
            unpack2(acc[bb][2], g0, g1); unpack2(acc[bb][3], o0, o1);
            unpack2(c2[bb], cc0, cc1);
            cc0 = sigf(f0) * cc0 + sigf(i0) * tanhf_(g0);
            cc1 = sigf(f1) * cc1 + sigf(i1) * tanhf_(g1);
            float h0 = sigf(o0) * tanhf_(cc0);
            float h1 = sigf(o1) * tanhf_(cc1);
            c2[bb] = pack2(cc0, cc1);
            int b = bg * 7 + bb;
            hs[(IN + 1 + hc0) * BPAD + b] = h0;
            hs[(IN + 2 + hc0) * BPAD + b] = h1;
            if (b0 + b < BATCH)
                *reinterpret_cast<float2*>(
                    &y[((size_t)(b0 + b) * SEQ + t) * 256 + dir * HID + hc0]) =
                    make_float2(h0, h1);
        }
        if (s < SEQ - 1)
            stage_x<IN>(src, hs, b0, dir ? (SEQ - 2 - s) : (s + 1), tid);
        __syncthreads();   // hs ready for next step
    }
}

__global__ void final_kernel(const float* __restrict__ y, const float* __restrict__ wout,
                             const float* __restrict__ bout, float* __restrict__ out)
{
    const int b = blockIdx.x;
    const int tid = threadIdx.x;
    const float* yr = y + (size_t)b * 15360;
    float s0 = 0.f, s1 = 0.f;
    for (int j = tid * 4; j < 15360; j += 128 * 4) {
        float4 v = *reinterpret_cast<const float4*>(&yr[j]);
        v.x = fmaxf(v.x, 0.f); v.y = fmaxf(v.y, 0.f);
        v.z = fmaxf(v.z, 0.f); v.w = fmaxf(v.w, 0.f);
        float4 w0 = __ldg(reinterpret_cast<const float4*>(&wout[j]));
        float4 w1 = __ldg(reinterpret_cast<const float4*>(&wout[15360 + j]));
        s0 += v.x * w0.x + v.y * w0.y + v.z * w0.z + v.w * w0.w;
        s1 += v.x * w1.x + v.y * w1.y + v.z * w1.z + v.w * w1.w;
    }
#pragma unroll
    for (int off = 16; off > 0; off >>= 1) {
        s0 += __shfl_down_sync(0xffffffffu, s0, off);
        s1 += __shfl_down_sync(0xffffffffu, s1, off);
    }
    __shared__ float r0[4], r1[4];
    int wid = tid >> 5;
    if ((tid & 31) == 0) { r0[wid] = s0; r1[wid] = s1; }
    __syncthreads();
    if (tid == 0) {
        out[(size_t)b * 2 + 0] = r0[0] + r0[1] + r0[2] + r0[3] + __ldg(&bout[0]);
        out[(size_t)b * 2 + 1] = r1[0] + r1[1] + r1[2] + r1[3] + __ldg(&bout[1]);
    }
}

extern "C" void kernel_launch(void* const* d_in, const int* in_sizes, int n_in,
                              void* d_out, int out_size) {
    const float* x = (const float*)d_in[0];
    WPtrs P;
    for (int i = 0; i < 6; i++) {
        P.w_ih[i] = (const float*)d_in[1 + 4 * i];
        P.w_hh[i] = (const float*)d_in[2 + 4 * i];
        P.b_ih[i] = (const float*)d_in[3 + 4 * i];
        P.b_hh[i] = (const float*)d_in[4 + 4 * i];
    }
    const float* w_out = (const float*)d_in[25];
    const float* b_out = (const float*)d_in[26];
    float* out = (float*)d_out;

    float *y0, *y1, *wc;
    cudaGetSymbolAddress((void**)&y0, g_y0);
    cudaGetSymbolAddress((void**)&y1, g_y1);
    cudaGetSymbolAddress((void**)&wc, g_wc);

    prep_kernel<<<(TOTALW + 255) / 256, 256>>>(P, wc);
    dummy_kernel<<<1, 32>>>();
    dummy_kernel<<<1, 32>>>();

    dim3 rg((BATCH + BT - 1) / BT, 2);   // (147, 2)
    lstm_fused<13><<<rg, 256>>>(x, wc, y0);
    lstm_fused<256><<<rg, 256>>>(y0, wc + SEG0, y1);
    lstm_fused<256><<<rg, 256>>>(y1, wc + SEG0 + 2 * (size_t)SEG12, y0);
    final_kernel<<<BATCH, 128>>>(y0, w_out, b_out, out);
}

// round 5
// speedup vs baseline: 1.6469x; 1.6469x over previous
#include <cuda_runtime.h>
#include <cuda_bf16.h>
#include <cstdint>
#include <cstddef>

#define BATCH 4096
#define SEQ   60
#define INP   13
#define HID   128
#define GATES 512
#define MROWS (BATCH*SEQ)
#define BT    32
#define HPAD  34

// B-fragment table: [layer(2)][dir(2)][kc(16)][n8(64)][lane(32)] x uint4
#define BF_PER_LAYER (2*16*64*32)          // uint4 count
#define BF_TOTAL     (2*BF_PER_LAYER)

__device__ float g_xp[(size_t)2 * MROWS * GATES];
__device__ float g_y0[(size_t)MROWS * 256];
__device__ float g_y1[(size_t)MROWS * 256];
__device__ float g_whhT[6 * HID * GATES];
__device__ float g_w0T [2 * INP * GATES];
__device__ uint4 g_bfrag[BF_TOTAL];

typedef unsigned long long ull;

__device__ __forceinline__ ull pack_dup(float x) {
    ull r; asm("mov.b64 %0, {%1, %1};" : "=l"(r) : "f"(x)); return r;
}
__device__ __forceinline__ ull pack2(float x, float y) {
    ull r; asm("mov.b64 %0, {%1, %2};" : "=l"(r) : "f"(x), "f"(y)); return r;
}
__device__ __forceinline__ void unpack2(ull v, float& x, float& y) {
    asm("mov.b64 {%0, %1}, %2;" : "=f"(x), "=f"(y) : "l"(v));
}
__device__ __forceinline__ void fma2(ull& d, ull a, ull b) {
    asm("fma.rn.f32x2 %0, %1, %2, %3;" : "=l"(d) : "l"(a), "l"(b), "l"(d));
}
__device__ __forceinline__ float sigf(float x) { return __fdividef(1.f, 1.f + __expf(-x)); }
__device__ __forceinline__ float tanhf_(float x) {
    float ax = fabsf(x); float e = __expf(-2.f * ax);
    return copysignf(__fdividef(1.f - e, 1.f + e), x);
}
__device__ __forceinline__ uint32_t pack_bf2(float a, float b) {
    __nv_bfloat162 t = __floats2bfloat162_rn(a, b);   // a -> low half
    return *reinterpret_cast<uint32_t*>(&t);
}
__device__ __forceinline__ void split_hl(float v, float& hi, float& lo) {
    __nv_bfloat16 h = __float2bfloat16_rn(v);
    hi = __bfloat162float(h);
    lo = v - hi;
}
__device__ __forceinline__ void mma16816(float c[4], const uint32_t a[4],
                                         uint32_t b0, uint32_t b1) {
    asm volatile("mma.sync.aligned.m16n8k16.row.col.f32.bf16.bf16.f32 "
                 "{%0,%1,%2,%3}, {%4,%5,%6,%7}, {%8,%9}, {%0,%1,%2,%3};"
                 : "+f"(c[0]), "+f"(c[1]), "+f"(c[2]), "+f"(c[3])
                 : "r"(a[0]), "r"(a[1]), "r"(a[2]), "r"(a[3]), "r"(b0), "r"(b1));
}
__device__ __forceinline__ void ldmx4(uint32_t r[4], const void* p) {
    uint32_t addr = (uint32_t)__cvta_generic_to_shared(p);
    asm volatile("ldmatrix.sync.aligned.m8n8.x4.shared.b16 {%0,%1,%2,%3}, [%4];"
                 : "=r"(r[0]), "=r"(r[1]), "=r"(r[2]), "=r"(r[3]) : "r"(addr));
}

struct WPtrs {
    const float* w_ih[6];
    const float* w_hh[6];
    const float* b_ih[6];
    const float* b_hh[6];
};

// ---- prep kernels ----
__global__ void prep_whh(WPtrs P, float* __restrict__ whhT) {
    int idx = blockIdx.x * 256 + threadIdx.x;
    if (idx >= 6 * HID * GATES) return;
    int w = idx / (HID * GATES), rem = idx % (HID * GATES);
    int k = rem / GATES, j = rem % GATES;
    whhT[idx] = P.w_hh[w][j * HID + k];
}
__global__ void prep_w0(WPtrs P, float* __restrict__ w0T) {
    int idx = blockIdx.x * 256 + threadIdx.x;
    if (idx >= 2 * INP * GATES) return;
    int w = idx / (INP * GATES), rem = idx % (INP * GATES);
    int k = rem / GATES, j = rem % GATES;
    w0T[idx] = P.w_ih[w][j * INP + k];
}
// bf16 hi/lo B fragments for layers 1,2 (w_ih indices 2..5), fragment-linear.
__global__ void prep_bfrag(WPtrs P, uint4* __restrict__ bf) {
    int idx = blockIdx.x * 256 + threadIdx.x;
    if (idx >= BF_TOTAL) return;
    int lane = idx & 31;
    int n8   = (idx >> 5) & 63;
    int kc   = (idx >> 11) & 15;
    int dir  = (idx >> 15) & 1;
    int layer = idx >> 16;
    const float* W = P.w_ih[2 + layer * 2 + dir];   // [512][256]
    int n = n8 * 8 + (lane >> 2);
    int kb = kc * 16 + (lane & 3) * 2;
    float v00 = W[n * 256 + kb + 0], v01 = W[n * 256 + kb + 1];
    float v10 = W[n * 256 + kb + 8], v11 = W[n * 256 + kb + 9];
    float h00, l00, h01, l01, h10, l10, h11, l11;
    split_hl(v00, h00, l00); split_hl(v01, h01, l01);
    split_hl(v10, h10, l10); split_hl(v11, h11, l11);
    uint4 o;
    o.x = pack_bf2(h00, h01);   // b0 hi
    o.y = pack_bf2(h10, h11);   // b1 hi
    o.z = pack_bf2(l00, l01);   // b0 lo
    o.w = pack_bf2(l10, l11);   // b1 lo
    bf[idx] = o;
}

// ---- split-bf16 tensor-core projection GEMM ----
// xp[dir][m][n] = A[m][0:256] . W[n][0:256]^T + bih[n] + bhh[n]
__global__ __launch_bounds__(256, 1)
void gemm_mma(const float* __restrict__ A,          // [MROWS][256]
              const uint4* __restrict__ bfrag,      // layer base
              const float* __restrict__ bihF, const float* __restrict__ bhhF,
              const float* __restrict__ bihB, const float* __restrict__ bhhB,
              float* __restrict__ xp)
{
    const int dir = blockIdx.z;
    const int m0  = blockIdx.x * 128;
    const int n0  = blockIdx.y * 128;
    const int tid = threadIdx.x;
    const int lane = tid & 31, wid = tid >> 5;
    const int wm = wid & 3, wn = wid >> 2;
    const float* bih = dir ? bihB : bihF;
    const float* bhh = dir ? bhhB : bhhF;

    __shared__ __align__(16) uint16_t Asm[2][128][24];   // [hi/lo][row][16 + 8 pad]

    float acc[2][8][4];
#pragma unroll
    for (int a = 0; a < 2; a++)
#pragma unroll
        for (int b = 0; b < 8; b++)
#pragma unroll
            for (int c = 0; c < 4; c++) acc[a][b][c] = 0.f;

    // ldmatrix source rows for this thread
    const int lrow0 = wm * 32 + (lane & 7) + ((lane >> 3) & 1) * 8;
    const int lkb   = (lane & 16) ? 8 : 0;

    const int arow = tid & 127;
    const int ach  = tid >> 7;            // 0/1 -> k-cols 0-7 / 8-15

    for (int kc = 0; kc < 16; ++kc) {
        // stage + convert A chunk 128x16
        {
            const float4* src = reinterpret_cast<const float4*>(
                &A[(size_t)(m0 + arow) * 256 + kc * 16 + ach * 8]);
            float4 v0 = src[0], v1 = src[1];
            float hv[8], lv[8];
            split_hl(v0.x, hv[0], lv[0]); split_hl(v0.y, hv[1], lv[1]);
            split_hl(v0.z, hv[2], lv[2]); split_hl(v0.w, hv[3], lv[3]);
            split_hl(v1.x, hv[4], lv[4]); split_hl(v1.y, hv[5], lv[5]);
            split_hl(v1.z, hv[6], lv[6]); split_hl(v1.w, hv[7], lv[7]);
            uint4 ph, pl;
            ph.x = pack_bf2(hv[0], hv[1]); ph.y = pack_bf2(hv[2], hv[3]);
            ph.z = pack_bf2(hv[4], hv[5]); ph.w = pack_bf2(hv[6], hv[7]);
            pl.x = pack_bf2(lv[0], lv[1]); pl.y = pack_bf2(lv[2], lv[3]);
            pl.z = pack_bf2(lv[4], lv[5]); pl.w = pack_bf2(lv[6], lv[7]);
            *reinterpret_cast<uint4*>(&Asm[0][arow][ach * 8]) = ph;
            *reinterpret_cast<uint4*>(&Asm[1][arow][ach * 8]) = pl;
        }
        __syncthreads();

        // B fragments (hi+lo in one LDG.128)
        uint4 bf[8];
        const int nbase = blockIdx.y * 16 + wn * 8;
#pragma unroll
        for (int i = 0; i < 8; ++i)
            bf[i] = bfrag[(((size_t)(dir * 16 + kc) * 64) + nbase + i) * 32 + lane];

        // A fragments
        uint32_t ah[2][4], al[2][4];
#pragma unroll
        for (int ms = 0; ms < 2; ++ms) {
            ldmx4(ah[ms], &Asm[0][lrow0 + ms * 16][lkb]);
            ldmx4(al[ms], &Asm[1][lrow0 + ms * 16][lkb]);
        }

#pragma unroll
        for (int i = 0; i < 8; ++i) {
#pragma unroll
            for (int ms = 0; ms < 2; ++ms) {
                mma16816(acc[ms][i], ah[ms], bf[i].x, bf[i].y);   // hi*hi
                mma16816(acc[ms][i], ah[ms], bf[i].z, bf[i].w);   // hi*lo
                mma16816(acc[ms][i], al[ms], bf[i].x, bf[i].y);   // lo*hi
            }
        }
        __syncthreads();
    }

    // epilogue
    const int g  = lane >> 2;
    const int t2 = (lane & 3) * 2;
#pragma unroll
    for (int ms = 0; ms < 2; ++ms) {
#pragma unroll
        for (int i = 0; i < 8; ++i) {
            int n = n0 + wn * 64 + i * 8 + t2;
            float b0 = bih[n] + bhh[n];
            float b1 = bih[n + 1] + bhh[n + 1];
            size_t r0 = (size_t)dir * MROWS + m0 + wm * 32 + ms * 16 + g;
            *reinterpret_cast<float2*>(&xp[r0 * 512 + n]) =
                make_float2(acc[ms][i][0] + b0, acc[ms][i][1] + b1);
            *reinterpret_cast<float2*>(&xp[(r0 + 8) * 512 + n]) =
                make_float2(acc[ms][i][2] + b0, acc[ms][i][3] + b1);
        }
    }
}

// ---- recurrence kernel (verbatim R3, known good) ----
__global__ __launch_bounds__(256, 2)
void lstm_rec_kernel(const float* __restrict__ xp, const float* __restrict__ x,
                     const float* __restrict__ w0T,
                     const float* __restrict__ bihF, const float* __restrict__ bhhF,
                     const float* __restrict__ bihB, const float* __restrict__ bhhB,
                     const float* __restrict__ whhTF, const float* __restrict__ whhTB,
                     float* __restrict__ y, int is_layer0)
{
    const int dir = blockIdx.y;
    const int b0  = blockIdx.x * BT;
    const int tid = threadIdx.x;
    const int bg  = tid >> 6;
    const int hc0 = (tid & 63) * 2;
    const float* whhT = dir ? whhTB : whhTF;

    __shared__ ull h2[128 * HPAD];
    __shared__ float xsm[BT][16];

    for (int i = tid; i < 128 * HPAD; i += 256) h2[i] = 0ull;

    ull c2[8];
#pragma unroll
    for (int i = 0; i < 8; i++) c2[i] = 0ull;

    ull bias2[4];
    const float* w0 = w0T + (size_t)dir * INP * GATES;
    if (is_layer0) {
        const float* bi = dir ? bihB : bihF;
        const float* bh = dir ? bhhB : bhhF;
#pragma unroll
        for (int g = 0; g < 4; g++) {
            int j = g * 128 + hc0;
            bias2[g] = pack2(bi[j] + bh[j], bi[j + 1] + bh[j + 1]);
        }
        int t0 = dir ? (SEQ - 1) : 0;
        for (int i = tid; i < BT * INP; i += 256) {
            int b = i / INP, q = i % INP;
            xsm[b][q] = x[((size_t)(b0 + b) * SEQ + t0) * INP + q];
        }
    }
    __syncthreads();

    const size_t xpdir = (size_t)dir * MROWS * GATES;

    for (int s = 0; s < SEQ; ++s) {
        const int t = dir ? (SEQ - 1 - s) : s;
        ull acc[8][4];

        if (is_layer0) {
#pragma unroll
            for (int bb = 0; bb < 8; ++bb)
#pragma unroll
                for (int g = 0; g < 4; ++g) acc[bb][g] = bias2[g];
#pragma unroll
            for (int q = 0; q < INP; ++q) {
                const ull* wq = reinterpret_cast<const ull*>(w0 + (size_t)q * GATES + hc0);
                ull w0v = wq[0], w1v = wq[64], w2v = wq[128], w3v = wq[192];
#pragma unroll
                for (int bb = 0; bb < 8; ++bb) {
                    ull xd = pack_dup(xsm[bg * 8 + bb][q]);
                    fma2(acc[bb][0], xd, w0v); fma2(acc[bb][1], xd, w1v);
                    fma2(acc[bb][2], xd, w2v); fma2(acc[bb][3], xd, w3v);
                }
            }
        } else {
#pragma unroll
            for (int bb = 0; bb < 8; ++bb) {
                const float* xpp = xp + xpdir + ((size_t)(b0 + bg * 8 + bb) * SEQ + t) * GATES + hc0;
#pragma unroll
                for (int g = 0; g < 4; ++g)
                    acc[bb][g] = *reinterpret_cast<const ull*>(xpp + g * 128);
            }
        }

        const float* wbase = whhT + hc0;
#pragma unroll 4
        for (int k = 0; k < HID; ++k) {
            const ull* wr = reinterpret_cast<const ull*>(wbase + (size_t)k * GATES);
            ull wv0 = wr[0], wv1 = wr[64], wv2 = wr[128], wv3 = wr[192];
            const ull* hrow = &h2[k * HPAD + (bg << 3)];
#pragma unroll
            for (int bb = 0; bb < 8; ++bb) {
                ull hv = hrow[bb];
                fma2(acc[bb][0], hv, wv0); fma2(acc[bb][1], hv, wv1);
                fma2(acc[bb][2], hv, wv2); fma2(acc[bb][3], hv, wv3);
            }
        }
        __syncthreads();

#pragma unroll
        for (int bb = 0; bb < 8; ++bb) {
            float i0, i1, f0, f1, g0, g1, o0, o1, cc0, cc1;
            unpack2(acc[bb][0], i0, i1); unpack2(acc[bb][1], f0, f1);
            unpack2(acc[bb][2], g0, g1); unpack2(acc[bb][3], o0, o1);
            unpack2(c2[bb], cc0, cc1);
            cc0 = sigf(f0) * cc0 + sigf(i0) * tanhf_(g0);
            cc1 = sigf(f1) * cc1 + sigf(i1) * tanhf_(g1);
            float h0 = sigf(o0) * tanhf_(cc0);
            float h1 = sigf(o1) * tanhf_(cc1);
            c2[bb] = pack2(cc0, cc1);
            int b = bg * 8 + bb;
            h2[(hc0)     * HPAD + b] = pack_dup(h0);
            h2[(hc0 + 1) * HPAD + b] = pack_dup(h1);
            *reinterpret_cast<float2*>(
                &y[((size_t)(b0 + b) * SEQ + t) * 256 + dir * 128 + hc0]) = make_float2(h0, h1);
        }
        if (is_layer0 && s < SEQ - 1) {
            int tn = dir ? (SEQ - 2 - s) : (s + 1);
            for (int i = tid; i < BT * INP; i += 256) {
                int b = i / INP, q = i % INP;
                xsm[b][q] = x[((size_t)(b0 + b) * SEQ + tn) * INP + q];
            }
        }
        __syncthreads();
    }
}

__global__ void final_kernel(const float* __restrict__ y, const float* __restrict__ wout,
                             const float* __restrict__ bout, float* __restrict__ out)
{
    const int b = blockIdx.x;
    const int tid = threadIdx.x;
    const float* yr = y + (size_t)b * 15360;
    float s0 = 0.f, s1 = 0.f;
    for (int j = tid * 4; j < 15360; j += 128 * 4) {
        float4 v = *reinterpret_cast<const float4*>(&yr[j]);
        v.x = fmaxf(v.x, 0.f); v.y = fmaxf(v.y, 0.f);
        v.z = fmaxf(v.z, 0.f); v.w = fmaxf(v.w, 0.f);
        float4 w0 = __ldg(reinterpret_cast<const float4*>(&wout[j]));
        float4 w1 = __ldg(reinterpret_cast<const float4*>(&wout[15360 + j]));
        s0 += v.x * w0.x + v.y * w0.y + v.z * w0.z + v.w * w0.w;
        s1 += v.x * w1.x + v.y * w1.y + v.z * w1.z + v.w * w1.w;
    }
#pragma unroll
    for (int off = 16; off > 0; off >>= 1) {
        s0 += __shfl_down_sync(0xffffffffu, s0, off);
        s1 += __shfl_down_sync(0xffffffffu, s1, off);
    }
    __shared__ float r0[4], r1[4];
    int wid = tid >> 5;
    if ((tid & 31) == 0) { r0[wid] = s0; r1[wid] = s1; }
    __syncthreads();
    if (tid == 0) {
        out[(size_t)b * 2 + 0] = r0[0] + r0[1] + r0[2] + r0[3] + __ldg(&bout[0]);
        out[(size_t)b * 2 + 1] = r1[0] + r1[1] + r1[2] + r1[3] + __ldg(&bout[1]);
    }
}

extern "C" void kernel_launch(void* const* d_in, const int* in_sizes, int n_in,
                              void* d_out, int out_size) {
    const float* x = (const float*)d_in[0];
    WPtrs P;
    for (int i = 0; i < 6; i++) {
        P.w_ih[i] = (const float*)d_in[1 + 4 * i];
        P.w_hh[i] = (const float*)d_in[2 + 4 * i];
        P.b_ih[i] = (const float*)d_in[3 + 4 * i];
        P.b_hh[i] = (const float*)d_in[4 + 4 * i];
    }
    const float* w_out = (const float*)d_in[25];
    const float* b_out = (const float*)d_in[26];
    float* out = (float*)d_out;

    float *xp, *y0, *y1, *whhT, *w0T; uint4* bfrag;
    cudaGetSymbolAddress((void**)&xp,    g_xp);
    cudaGetSymbolAddress((void**)&y0,    g_y0);
    cudaGetSymbolAddress((void**)&y1,    g_y1);
    cudaGetSymbolAddress((void**)&whhT,  g_whhT);
    cudaGetSymbolAddress((void**)&w0T,   g_w0T);
    cudaGetSymbolAddress((void**)&bfrag, g_bfrag);

    prep_whh<<<(6 * HID * GATES + 255) / 256, 256>>>(P, whhT);        // launch 0
    prep_w0<<<(2 * INP * GATES + 255) / 256, 256>>>(P, w0T);          // launch 1
    prep_bfrag<<<(BF_TOTAL + 255) / 256, 256>>>(P, bfrag);            // launch 2

    dim3 rgrid(BATCH / BT, 2);
    dim3 ggrid(MROWS / 128, GATES / 128, 2);

    // layer 0                                                         // launch 3
    lstm_rec_kernel<<<rgrid, 256>>>(nullptr, x, w0T,
                                    P.b_ih[0], P.b_hh[0], P.b_ih[1], P.b_hh[1],
                                    whhT + 0 * (size_t)HID * GATES, whhT + 1 * (size_t)HID * GATES,
                                    y0, 1);
    // layer 1                                                         // launches 4,5
    gemm_mma<<<ggrid, 256>>>(y0, bfrag,
                             P.b_ih[2], P.b_hh[2], P.b_ih[3], P.b_hh[3], xp);
    lstm_rec_kernel<<<rgrid, 256>>>(xp, nullptr, nullptr,
                                    P.b_ih[2], P.b_hh[2], P.b_ih[3], P.b_hh[3],
                                    whhT + 2 * (size_t)HID * GATES, whhT + 3 * (size_t)HID * GATES,
                                    y1, 0);
    // layer 2                                                         // launches 6,7
    gemm_mma<<<ggrid, 256>>>(y1, bfrag + BF_PER_LAYER,
                             P.b_ih[4], P.b_hh[4], P.b_ih[5], P.b_hh[5], xp);
    lstm_rec_kernel<<<rgrid, 256>>>(xp, nullptr, nullptr,
                                    P.b_ih[4], P.b_hh[4], P.b_ih[5], P.b_hh[5],
                                    whhT + 4 * (size_t)HID * GATES, whhT + 5 * (size_t)HID * GATES,
                                    y0, 0);
    final_kernel<<<BATCH, 128>>>(y0, w_out, b_out, out);               // launch 8
}

// round 6
// speedup vs baseline: 1.6657x; 1.0114x over previous
#include <cuda_runtime.h>
#include <cuda_bf16.h>
#include <cstdint>
#include <cstddef>

#define BATCH 4096
#define SEQ   60
#define INP   13
#define HID   128
#define GATES 512
#define MROWS (BATCH*SEQ)
#define BT    32
#define HPAD  34

#define BF_PER_LAYER (2*16*64*32)
#define BF_TOTAL     (2*BF_PER_LAYER)

__device__ float g_xp[(size_t)2 * MROWS * GATES];
__device__ float g_y0[(size_t)MROWS * 256];
__device__ float g_y1[(size_t)MROWS * 256];
__device__ float g_whhP[6 * HID * GATES];   // packed per-thread layout
__device__ float g_w0P [2 * INP * GATES];   // packed per-thread layout
__device__ uint4 g_bfrag[BF_TOTAL];

typedef unsigned long long ull;

__device__ __forceinline__ ull pack_dup(float x) {
    ull r; asm("mov.b64 %0, {%1, %1};" : "=l"(r) : "f"(x)); return r;
}
__device__ __forceinline__ ull pack2(float x, float y) {
    ull r; asm("mov.b64 %0, {%1, %2};" : "=l"(r) : "f"(x), "f"(y)); return r;
}
__device__ __forceinline__ void unpack2(ull v, float& x, float& y) {
    asm("mov.b64 {%0, %1}, %2;" : "=f"(x), "=f"(y) : "l"(v));
}
__device__ __forceinline__ void fma2(ull& d, ull a, ull b) {
    asm("fma.rn.f32x2 %0, %1, %2, %3;" : "=l"(d) : "l"(a), "l"(b), "l"(d));
}
__device__ __forceinline__ float sigf(float x) { return __fdividef(1.f, 1.f + __expf(-x)); }
__device__ __forceinline__ float tanhf_(float x) {
    float ax = fabsf(x); float e = __expf(-2.f * ax);
    return copysignf(__fdividef(1.f - e, 1.f + e), x);
}
__device__ __forceinline__ uint32_t pack_bf2(float a, float b) {
    __nv_bfloat162 t = __floats2bfloat162_rn(a, b);
    return *reinterpret_cast<uint32_t*>(&t);
}
__device__ __forceinline__ void split_hl(float v, float& hi, float& lo) {
    __nv_bfloat16 h = __float2bfloat16_rn(v);
    hi = __bfloat162float(h);
    lo = v - hi;
}
__device__ __forceinline__ void mma16816(float c[4], const uint32_t a[4],
                                         uint32_t b0, uint32_t b1) {
    asm volatile("mma.sync.aligned.m16n8k16.row.col.f32.bf16.bf16.f32 "
                 "{%0,%1,%2,%3}, {%4,%5,%6,%7}, {%8,%9}, {%0,%1,%2,%3};"
                 : "+f"(c[0]), "+f"(c[1]), "+f"(c[2]), "+f"(c[3])
                 : "r"(a[0]), "r"(a[1]), "r"(a[2]), "r"(a[3]), "r"(b0), "r"(b1));
}
__device__ __forceinline__ void ldmx4(uint32_t r[4], const void* p) {
    uint32_t addr = (uint32_t)__cvta_generic_to_shared(p);
    asm volatile("ldmatrix.sync.aligned.m8n8.x4.shared.b16 {%0,%1,%2,%3}, [%4];"
                 : "=r"(r[0]), "=r"(r[1]), "=r"(r[2]), "=r"(r[3]) : "r"(addr));
}

struct WPtrs {
    const float* w_ih[6];
    const float* w_hh[6];
    const float* b_ih[6];
    const float* b_hh[6];
};

// packed layout: i = p*8 + g*2 + e  <->  gate element j = g*128 + p*2 + e
__global__ void prep_whhP(WPtrs P, float* __restrict__ dst) {
    int idx = blockIdx.x * 256 + threadIdx.x;
    if (idx >= 6 * HID * GATES) return;
    int w = idx / (HID * GATES), rem = idx % (HID * GATES);
    int k = rem / GATES, i = rem % GATES;
    int p = i >> 3, g = (i & 7) >> 1, e = i & 1;
    int j = g * 128 + p * 2 + e;
    dst[idx] = P.w_hh[w][j * HID + k];
}
__global__ void prep_w0P(WPtrs P, float* __restrict__ dst) {
    int idx = blockIdx.x * 256 + threadIdx.x;
    if (idx >= 2 * INP * GATES) return;
    int w = idx / (INP * GATES), rem = idx % (INP * GATES);
    int q = rem / GATES, i = rem % GATES;
    int p = i >> 3, g = (i & 7) >> 1, e = i & 1;
    int j = g * 128 + p * 2 + e;
    dst[idx] = P.w_ih[w][j * INP + q];
}
__global__ void prep_bfrag(WPtrs P, uint4* __restrict__ bf) {
    int idx = blockIdx.x * 256 + threadIdx.x;
    if (idx >= BF_TOTAL) return;
    int lane = idx & 31;
    int n8   = (idx >> 5) & 63;
    int kc   = (idx >> 11) & 15;
    int dir  = (idx >> 15) & 1;
    int layer = idx >> 16;
    const float* W = P.w_ih[2 + layer * 2 + dir];
    int n = n8 * 8 + (lane >> 2);
    int kb = kc * 16 + (lane & 3) * 2;
    float v00 = W[n * 256 + kb + 0], v01 = W[n * 256 + kb + 1];
    float v10 = W[n * 256 + kb + 8], v11 = W[n * 256 + kb + 9];
    float h00, l00, h01, l01, h10, l10, h11, l11;
    split_hl(v00, h00, l00); split_hl(v01, h01, l01);
    split_hl(v10, h10, l10); split_hl(v11, h11, l11);
    uint4 o;
    o.x = pack_bf2(h00, h01); o.y = pack_bf2(h10, h11);
    o.z = pack_bf2(l00, l01); o.w = pack_bf2(l10, l11);
    bf[idx] = o;
}

// ---- split-bf16 tensor-core projection GEMM (unchanged from R5) ----
__global__ __launch_bounds__(256, 1)
void gemm_mma(const float* __restrict__ A,
              const uint4* __restrict__ bfrag,
              const float* __restrict__ bihF, const float* __restrict__ bhhF,
              const float* __restrict__ bihB, const float* __restrict__ bhhB,
              float* __restrict__ xp)
{
    const int dir = blockIdx.z;
    const int m0  = blockIdx.x * 128;
    const int n0  = blockIdx.y * 128;
    const int tid = threadIdx.x;
    const int lane = tid & 31, wid = tid >> 5;
    const int wm = wid & 3, wn = wid >> 2;
    const float* bih = dir ? bihB : bihF;
    const float* bhh = dir ? bhhB : bhhF;

    __shared__ __align__(16) uint16_t Asm[2][128][24];

    float acc[2][8][4];
#pragma unroll
    for (int a = 0; a < 2; a++)
#pragma unroll
        for (int b = 0; b < 8; b++)
#pragma unroll
            for (int c = 0; c < 4; c++) acc[a][b][c] = 0.f;

    const int lrow0 = wm * 32 + (lane & 7) + ((lane >> 3) & 1) * 8;
    const int lkb   = (lane & 16) ? 8 : 0;
    const int arow = tid & 127;
    const int ach  = tid >> 7;

    for (int kc = 0; kc < 16; ++kc) {
        {
            const float4* src = reinterpret_cast<const float4*>(
                &A[(size_t)(m0 + arow) * 256 + kc * 16 + ach * 8]);
            float4 v0 = src[0], v1 = src[1];
            float hv[8], lv[8];
            split_hl(v0.x, hv[0], lv[0]); split_hl(v0.y, hv[1], lv[1]);
            split_hl(v0.z, hv[2], lv[2]); split_hl(v0.w, hv[3], lv[3]);
            split_hl(v1.x, hv[4], lv[4]); split_hl(v1.y, hv[5], lv[5]);
            split_hl(v1.z, hv[6], lv[6]); split_hl(v1.w, hv[7], lv[7]);
            uint4 ph, pl;
            ph.x = pack_bf2(hv[0], hv[1]); ph.y = pack_bf2(hv[2], hv[3]);
            ph.z = pack_bf2(hv[4], hv[5]); ph.w = pack_bf2(hv[6], hv[7]);
            pl.x = pack_bf2(lv[0], lv[1]); pl.y = pack_bf2(lv[2], lv[3]);
            pl.z = pack_bf2(lv[4], lv[5]); pl.w = pack_bf2(lv[6], lv[7]);
            *reinterpret_cast<uint4*>(&Asm[0][arow][ach * 8]) = ph;
            *reinterpret_cast<uint4*>(&Asm[1][arow][ach * 8]) = pl;
        }
        __syncthreads();

        uint4 bf[8];
        const int nbase = blockIdx.y * 16 + wn * 8;
#pragma unroll
        for (int i = 0; i < 8; ++i)
            bf[i] = bfrag[(((size_t)(dir * 16 + kc) * 64) + nbase + i) * 32 + lane];

        uint32_t ah[2][4], al[2][4];
#pragma unroll
        for (int ms = 0; ms < 2; ++ms) {
            ldmx4(ah[ms], &Asm[0][lrow0 + ms * 16][lkb]);
            ldmx4(al[ms], &Asm[1][lrow0 + ms * 16][lkb]);
        }

#pragma unroll
        for (int i = 0; i < 8; ++i) {
#pragma unroll
            for (int ms = 0; ms < 2; ++ms) {
                mma16816(acc[ms][i], ah[ms], bf[i].x, bf[i].y);
                mma16816(acc[ms][i], ah[ms], bf[i].z, bf[i].w);
                mma16816(acc[ms][i], al[ms], bf[i].x, bf[i].y);
            }
        }
        __syncthreads();
    }

    const int g  = lane >> 2;
    const int t2 = (lane & 3) * 2;
#pragma unroll
    for (int ms = 0; ms < 2; ++ms) {
#pragma unroll
        for (int i = 0; i < 8; ++i) {
            int n = n0 + wn * 64 + i * 8 + t2;
            float b0 = bih[n] + bhh[n];
            float b1 = bih[n + 1] + bhh[n + 1];
            size_t r0 = (size_t)dir * MROWS + m0 + wm * 32 + ms * 16 + g;
            *reinterpret_cast<float2*>(&xp[r0 * 512 + n]) =
                make_float2(acc[ms][i][0] + b0, acc[ms][i][1] + b1);
            *reinterpret_cast<float2*>(&xp[(r0 + 8) * 512 + n]) =
                make_float2(acc[ms][i][2] + b0, acc[ms][i][3] + b1);
        }
    }
}

// ---- recurrence kernel: R3 structure + packed weight loads (2x LDG.128/k) ----
__global__ __launch_bounds__(256, 2)
void lstm_rec_kernel(const float* __restrict__ xp, const float* __restrict__ x,
                     const float* __restrict__ w0P,
                     const float* __restrict__ bihF, const float* __restrict__ bhhF,
                     const float* __restrict__ bihB, const float* __restrict__ bhhB,
                     const float* __restrict__ whhPF, const float* __restrict__ whhPB,
                     float* __restrict__ y, int is_layer0)
{
    const int dir = blockIdx.y;
    const int b0  = blockIdx.x * BT;
    const int tid = threadIdx.x;
    const int bg  = tid >> 6;
    const int p   = tid & 63;
    const int hc0 = p * 2;
    const float* whhP = dir ? whhPB : whhPF;

    __shared__ ull h2[128 * HPAD];
    __shared__ float xsm[BT][16];

    for (int i = tid; i < 128 * HPAD; i += 256) h2[i] = 0ull;

    ull c2[8];
#pragma unroll
    for (int i = 0; i < 8; i++) c2[i] = 0ull;

    ull bias2[4];
    const float* w0 = w0P + (size_t)dir * INP * GATES;
    if (is_layer0) {
        const float* bi = dir ? bihB : bihF;
        const float* bh = dir ? bhhB : bhhF;
#pragma unroll
        for (int g = 0; g < 4; g++) {
            int j = g * 128 + hc0;
            bias2[g] = pack2(bi[j] + bh[j], bi[j + 1] + bh[j + 1]);
        }
        int t0 = dir ? (SEQ - 1) : 0;
        for (int i = tid; i < BT * INP; i += 256) {
            int b = i / INP, q = i % INP;
            xsm[b][q] = x[((size_t)(b0 + b) * SEQ + t0) * INP + q];
        }
    }
    __syncthreads();

    const size_t xpdir = (size_t)dir * MROWS * GATES;

    for (int s = 0; s < SEQ; ++s) {
        const int t = dir ? (SEQ - 1 - s) : s;
        ull acc[8][4];

        if (is_layer0) {
#pragma unroll
            for (int bb = 0; bb < 8; ++bb)
#pragma unroll
                for (int g = 0; g < 4; ++g) acc[bb][g] = bias2[g];
#pragma unroll
            for (int q = 0; q < INP; ++q) {
                const ulonglong2* wq =
                    reinterpret_cast<const ulonglong2*>(w0 + (size_t)q * GATES + p * 8);
                ulonglong2 u0 = wq[0], u1 = wq[1];
#pragma unroll
                for (int bb = 0; bb < 8; ++bb) {
                    ull xd = pack_dup(xsm[bg * 8 + bb][q]);
                    fma2(acc[bb][0], xd, u0.x); fma2(acc[bb][1], xd, u0.y);
                    fma2(acc[bb][2], xd, u1.x); fma2(acc[bb][3], xd, u1.y);
                }
            }
        } else {
#pragma unroll
            for (int bb = 0; bb < 8; ++bb) {
                const float* xpp = xp + xpdir + ((size_t)(b0 + bg * 8 + bb) * SEQ + t) * GATES + hc0;
#pragma unroll
                for (int g = 0; g < 4; ++g)
                    acc[bb][g] = *reinterpret_cast<const ull*>(xpp + g * 128);
            }
        }

        const float* wbase = whhP + p * 8;
#pragma unroll 4
        for (int k = 0; k < HID; ++k) {
            const ulonglong2* wr =
                reinterpret_cast<const ulonglong2*>(wbase + (size_t)k * GATES);
            ulonglong2 u0 = wr[0], u1 = wr[1];
            const ull* hrow = &h2[k * HPAD + (bg << 3)];
#pragma unroll
            for (int bb = 0; bb < 8; ++bb) {
                ull hv = hrow[bb];
                fma2(acc[bb][0], hv, u0.x); fma2(acc[bb][1], hv, u0.y);
                fma2(acc[bb][2], hv, u1.x); fma2(acc[bb][3], hv, u1.y);
            }
        }
        __syncthreads();

#pragma unroll
        for (int bb = 0; bb < 8; ++bb) {
            float i0, i1, f0, f1, g0, g1, o0, o1, cc0, cc1;
            unpack2(acc[bb][0], i0, i1); unpack2(acc[bb][1], f0, f1);
            unpack2(acc[bb][2], g0, g1); unpack2(acc[bb][3], o0, o1);
            unpack2(c2[bb], cc0, cc1);
            cc0 = sigf(f0) * cc0 + sigf(i0) * tanhf_(g0);
            cc1 = sigf(f1) * cc1 + sigf(i1) * tanhf_(g1);
            float h0 = sigf(o0) * tanhf_(cc0);
            float h1 = sigf(o1) * tanhf_(cc1);
            c2[bb] = pack2(cc0, cc1);
            int b = bg * 8 + bb;
            h2[(hc0)     * HPAD + b] = pack_dup(h0);
            h2[(hc0 + 1) * HPAD + b] = pack_dup(h1);
            *reinterpret_cast<float2*>(
                &y[((size_t)(b0 + b) * SEQ + t) * 256 + dir * 128 + hc0]) = make_float2(h0, h1);
        }
        if (is_layer0 && s < SEQ - 1) {
            int tn = dir ? (SEQ - 2 - s) : (s + 1);
            for (int i = tid; i < BT * INP; i += 256) {
                int b = i / INP, q = i % INP;
                xsm[b][q] = x[((size_t)(b0 + b) * SEQ + tn) * INP + q];
            }
        }
        __syncthreads();
    }
}

__global__ void final_kernel(const float* __restrict__ y, const float* __restrict__ wout,
                             const float* __restrict__ bout, float* __restrict__ out)
{
    const int b = blockIdx.x;
    const int tid = threadIdx.x;
    const float* yr = y + (size_t)b * 15360;
    float s0 = 0.f, s1 = 0.f;
    for (int j = tid * 4; j < 15360; j += 128 * 4) {
        float4 v = *reinterpret_cast<const float4*>(&yr[j]);
        v.x = fmaxf(v.x, 0.f); v.y = fmaxf(v.y, 0.f);
        v.z = fmaxf(v.z, 0.f); v.w = fmaxf(v.w, 0.f);
        float4 w0 = __ldg(reinterpret_cast<const float4*>(&wout[j]));
        float4 w1 = __ldg(reinterpret_cast<const float4*>(&wout[15360 + j]));
        s0 += v.x * w0.x + v.y * w0.y + v.z * w0.z + v.w * w0.w;
        s1 += v.x * w1.x + v.y * w1.y + v.z * w1.z + v.w * w1.w;
    }
#pragma unroll
    for (int off = 16; off > 0; off >>= 1) {
        s0 += __shfl_down_sync(0xffffffffu, s0, off);
        s1 += __shfl_down_sync(0xffffffffu, s1, off);
    }
    __shared__ float r0[4], r1[4];
    int wid = tid >> 5;
    if ((tid & 31) == 0) { r0[wid] = s0; r1[wid] = s1; }
    __syncthreads();
    if (tid == 0) {
        out[(size_t)b * 2 + 0] = r0[0] + r0[1] + r0[2] + r0[3] + __ldg(&bout[0]);
        out[(size_t)b * 2 + 1] = r1[0] + r1[1] + r1[2] + r1[3] + __ldg(&bout[1]);
    }
}

extern "C" void kernel_launch(void* const* d_in, const int* in_sizes, int n_in,
                              void* d_out, int out_size) {
    const float* x = (const float*)d_in[0];
    WPtrs P;
    for (int i = 0; i < 6; i++) {
        P.w_ih[i] = (const float*)d_in[1 + 4 * i];
        P.w_hh[i] = (const float*)d_in[2 + 4 * i];
        P.b_ih[i] = (const float*)d_in[3 + 4 * i];
        P.b_hh[i] = (const float*)d_in[4 + 4 * i];
    }
    const float* w_out = (const float*)d_in[25];
    const float* b_out = (const float*)d_in[26];
    float* out = (float*)d_out;

    float *xp, *y0, *y1, *whhP, *w0P; uint4* bfrag;
    cudaGetSymbolAddress((void**)&xp,    g_xp);
    cudaGetSymbolAddress((void**)&y0,    g_y0);
    cudaGetSymbolAddress((void**)&y1,    g_y1);
    cudaGetSymbolAddress((void**)&whhP,  g_whhP);
    cudaGetSymbolAddress((void**)&w0P,   g_w0P);
    cudaGetSymbolAddress((void**)&bfrag, g_bfrag);

    prep_whhP<<<(6 * HID * GATES + 255) / 256, 256>>>(P, whhP);       // 0
    prep_w0P<<<(2 * INP * GATES + 255) / 256, 256>>>(P, w0P);         // 1
    prep_bfrag<<<(BF_TOTAL + 255) / 256, 256>>>(P, bfrag);            // 2

    dim3 rgrid(BATCH / BT, 2);
    dim3 ggrid(MROWS / 128, GATES / 128, 2);

    lstm_rec_kernel<<<rgrid, 256>>>(nullptr, x, w0P,                  // 3
                                    P.b_ih[0], P.b_hh[0], P.b_ih[1], P.b_hh[1],
                                    whhP + 0 * (size_t)HID * GATES, whhP + 1 * (size_t)HID * GATES,
                                    y0, 1);
    gemm_mma<<<ggrid, 256>>>(y0, bfrag,                               // 4
                             P.b_ih[2], P.b_hh[2], P.b_ih[3], P.b_hh[3], xp);
    lstm_rec_kernel<<<rgrid, 256>>>(xp, nullptr, nullptr,             // 5  (ncu -s 5)
                                    P.b_ih[2], P.b_hh[2], P.b_ih[3], P.b_hh[3],
                                    whhP + 2 * (size_t)HID * GATES, whhP + 3 * (size_t)HID * GATES,
                                    y1, 0);
    gemm_mma<<<ggrid, 256>>>(y1, bfrag + BF_PER_LAYER,                // 6
                             P.b_ih[4], P.b_hh[4], P.b_ih[5], P.b_hh[5], xp);
    lstm_rec_kernel<<<rgrid, 256>>>(xp, nullptr, nullptr,             // 7
                                    P.b_ih[4], P.b_hh[4], P.b_ih[5], P.b_hh[5],
                                    whhP + 4 * (size_t)HID * GATES, whhP + 5 * (size_t)HID * GATES,
                                    y0, 0);
    final_kernel<<<BATCH, 128>>>(y0, w_out, b_out, out);              // 8
}